// round 1
// baseline (speedup 1.0000x reference)
#include <cuda_runtime.h>

#define N_NODES 25000
#define E_EDGES 400000
#define F_IN_   133
#define H_      8
#define C_      64
#define HC_     512
#define BN_EPS_ 1e-5f
#define NEG_SLOPE_ 0.2f

// ---------------- device scratch (static: no runtime allocation) ------------
__device__ float g_xl[(size_t)N_NODES * HC_];   // x @ Wl   (51.2 MB)
__device__ float g_xr[(size_t)N_NODES * HC_];   // x @ Wr   (51.2 MB)
__device__ int   g_counts[N_NODES];
__device__ int   g_offsets[N_NODES + 1];
__device__ int   g_cursor[N_NODES];
__device__ int   g_csr_src[E_EDGES];
__device__ float g_gout[N_NODES];               // (post GAT/BN/PReLU) @ Wg
__device__ float g_dinv[N_NODES];               // rsqrt(in-degree incl self)

typedef unsigned long long u64;

__device__ __forceinline__ u64 pack2(float lo, float hi) {
    u64 r; asm("mov.b64 %0, {%1, %2};" : "=l"(r) : "f"(lo), "f"(hi)); return r;
}
__device__ __forceinline__ void ffma2(u64& d, u64 a, u64 b) {
    asm("fma.rn.f32x2 %0, %1, %2, %0;" : "+l"(d) : "l"(a), "l"(b));
}
__device__ __forceinline__ float2 unpack2(u64 v) {
    float2 f; asm("mov.b64 {%0, %1}, %2;" : "=f"(f.x), "=f"(f.y) : "l"(v)); return f;
}

// ---------------- GEMM: g_xl = x@Wl, g_xr = x@Wr (blockIdx.z selects) -------
#define BM 128
#define BN 128
#define BK 8

__global__ __launch_bounds__(256) void gemm_xlxr(
    const float* __restrict__ x,
    const float* __restrict__ Wl,
    const float* __restrict__ Wr)
{
    const float* __restrict__ W = (blockIdx.z == 0) ? Wl : Wr;
    float* out = (blockIdx.z == 0) ? g_xl : g_xr;

    const int row0 = blockIdx.x * BM;
    const int col0 = blockIdx.y * BN;

    __shared__ float As[BK][BM];
    __shared__ float Bs[BK][BN];

    const int t  = threadIdx.x;
    const int tx = t & 15;          // 16 col groups of 8
    const int ty = t >> 4;          // 16 row groups of 8

    // global->shared load mapping
    const int lmA = t >> 1;         // 0..127 : tile row
    const int lkA = (t & 1) * 4;    // 0 or 4 : k offset
    const int lkB = t >> 5;         // 0..7
    const int lnB = (t & 31) * 4;   // 0..124

    u64 acc[8][4];
    #pragma unroll
    for (int i = 0; i < 8; i++) {
        #pragma unroll
        for (int j = 0; j < 4; j++) acc[i][j] = 0ull;   // {+0.f,+0.f}
    }

    for (int k0 = 0; k0 < F_IN_; k0 += BK) {
        // As[k][m] = x[row0+m][k0+k]
        {
            const int row = row0 + lmA;
            const bool rok = row < N_NODES;
            const float* xp = x + (size_t)row * F_IN_ + k0 + lkA;
            #pragma unroll
            for (int i = 0; i < 4; i++) {
                int kk = k0 + lkA + i;
                As[lkA + i][lmA] = (rok && kk < F_IN_) ? xp[i] : 0.f;
            }
        }
        // Bs[k][n] = W[k0+k][col0+n]
        {
            int kk = k0 + lkB;
            float4 v = make_float4(0.f, 0.f, 0.f, 0.f);
            if (kk < F_IN_)
                v = *(const float4*)(W + (size_t)kk * HC_ + col0 + lnB);
            *(float4*)&Bs[lkB][lnB] = v;
        }
        __syncthreads();

        #pragma unroll
        for (int k = 0; k < BK; k++) {
            float4 a0 = *(const float4*)&As[k][ty * 8];
            float4 a1 = *(const float4*)&As[k][ty * 8 + 4];
            const u64* bp = (const u64*)&Bs[k][tx * 8];
            u64 b0 = bp[0], b1 = bp[1], b2 = bp[2], b3 = bp[3];
            u64 ap[8];
            ap[0] = pack2(a0.x, a0.x); ap[1] = pack2(a0.y, a0.y);
            ap[2] = pack2(a0.z, a0.z); ap[3] = pack2(a0.w, a0.w);
            ap[4] = pack2(a1.x, a1.x); ap[5] = pack2(a1.y, a1.y);
            ap[6] = pack2(a1.z, a1.z); ap[7] = pack2(a1.w, a1.w);
            #pragma unroll
            for (int i = 0; i < 8; i++) {
                ffma2(acc[i][0], ap[i], b0);
                ffma2(acc[i][1], ap[i], b1);
                ffma2(acc[i][2], ap[i], b2);
                ffma2(acc[i][3], ap[i], b3);
            }
        }
        __syncthreads();
    }

    #pragma unroll
    for (int i = 0; i < 8; i++) {
        int row = row0 + ty * 8 + i;
        if (row < N_NODES) {
            float* op = out + (size_t)row * HC_ + col0 + tx * 8;
            float2 f0 = unpack2(acc[i][0]);
            float2 f1 = unpack2(acc[i][1]);
            float2 f2 = unpack2(acc[i][2]);
            float2 f3 = unpack2(acc[i][3]);
            *(float4*)(op)     = make_float4(f0.x, f0.y, f1.x, f1.y);
            *(float4*)(op + 4) = make_float4(f2.x, f2.y, f3.x, f3.y);
        }
    }
}

// ---------------- CSR build -------------------------------------------------
__global__ void zero_counts_kernel() {
    int i = blockIdx.x * blockDim.x + threadIdx.x;
    if (i < N_NODES) g_counts[i] = 0;
}

__global__ void hist_kernel(const int* __restrict__ ei) {
    int e = blockIdx.x * blockDim.x + threadIdx.x;
    if (e < E_EDGES) atomicAdd(&g_counts[ei[E_EDGES + e]], 1);
}

__global__ __launch_bounds__(1024) void scan_kernel() {
    __shared__ int sh[1024];
    __shared__ int s_carry;
    const int t = threadIdx.x;
    if (t == 0) { s_carry = 0; g_offsets[0] = 0; }
    __syncthreads();
    for (int base = 0; base < N_NODES; base += 1024) {
        int i = base + t;
        int v = (i < N_NODES) ? g_counts[i] : 0;
        sh[t] = v;
        __syncthreads();
        #pragma unroll
        for (int d = 1; d < 1024; d <<= 1) {
            int val = sh[t];
            int add = (t >= d) ? sh[t - d] : 0;
            __syncthreads();
            sh[t] = val + add;
            __syncthreads();
        }
        int incl = sh[t];
        int carry = s_carry;
        if (i < N_NODES) {
            g_offsets[i + 1] = carry + incl;
            g_cursor[i] = carry + incl - v;    // exclusive prefix
        }
        __syncthreads();
        if (t == 1023) s_carry = carry + incl;
        __syncthreads();
    }
}

__global__ void scatter_kernel(const int* __restrict__ ei) {
    int e = blockIdx.x * blockDim.x + threadIdx.x;
    if (e < E_EDGES) {
        int d = ei[E_EDGES + e];
        int p = atomicAdd(&g_cursor[d], 1);
        g_csr_src[p] = ei[e];
    }
}

// ---------------- GATv2 aggregation + b1 + BN + PReLU + (.@Wg) --------------
// One block (128 threads) per dst node. Thread t owns channels [4t, 4t+4)
// (head h = t/16, so 16-lane shfl groups are head-aligned). Online softmax.
__global__ __launch_bounds__(128) void agg_kernel(
    const float* __restrict__ att,  const float* __restrict__ b1,
    const float* __restrict__ bn_g, const float* __restrict__ bn_b,
    const float* __restrict__ bn_m, const float* __restrict__ bn_v,
    const float* __restrict__ prelu_w, const float* __restrict__ Wg)
{
    const int node = blockIdx.x;
    const int t = threadIdx.x;
    const float4* __restrict__ xl4 = (const float4*)g_xl;

    const float4 xr_v  = ((const float4*)(g_xr + (size_t)node * HC_))[t];
    const float4 att_v = ((const float4*)att)[t];

    const int rs = g_offsets[node];
    const int re = g_offsets[node + 1];
    const int cnt = re - rs + 1;               // incl self loop

    float a0 = 0.f, a1 = 0.f, a2 = 0.f, a3 = 0.f;
    float m = __int_as_float(0xff800000);      // -inf
    float den = 0.f;

    // first "edge" is the self loop
    float4 v = __ldg(&xl4[(size_t)node * (HC_ / 4) + t]);
    for (int k = 0; k < cnt; k++) {
        float4 nv = v;
        if (k + 1 < cnt) {
            int ns = g_csr_src[rs + k];
            nv = __ldg(&xl4[(size_t)ns * (HC_ / 4) + t]);
        }
        float s0 = v.x + xr_v.x; s0 = s0 > 0.f ? s0 : NEG_SLOPE_ * s0;
        float s1 = v.y + xr_v.y; s1 = s1 > 0.f ? s1 : NEG_SLOPE_ * s1;
        float s2 = v.z + xr_v.z; s2 = s2 > 0.f ? s2 : NEG_SLOPE_ * s2;
        float s3 = v.w + xr_v.w; s3 = s3 > 0.f ? s3 : NEG_SLOPE_ * s3;
        float p = att_v.x * s0 + att_v.y * s1 + att_v.z * s2 + att_v.w * s3;
        p += __shfl_xor_sync(0xffffffffu, p, 1);
        p += __shfl_xor_sync(0xffffffffu, p, 2);
        p += __shfl_xor_sync(0xffffffffu, p, 4);
        p += __shfl_xor_sync(0xffffffffu, p, 8);   // per-head score e, all lanes
        float e  = p;
        float mn = fmaxf(m, e);
        float sc = __expf(m - mn);                 // 1 if m >= e; 0 on first iter
        float w  = __expf(e - mn);
        den = den * sc + w;
        a0 = a0 * sc + w * v.x;
        a1 = a1 * sc + w * v.y;
        a2 = a2 * sc + w * v.z;
        a3 = a3 * sc + w * v.w;
        m = mn;
        v = nv;
    }

    const float inv = 1.f / den;
    const float4 b1v = ((const float4*)b1)[t];
    const float4 gmv = ((const float4*)bn_g)[t];
    const float4 btv = ((const float4*)bn_b)[t];
    const float4 mnv = ((const float4*)bn_m)[t];
    const float4 vrv = ((const float4*)bn_v)[t];
    const float pw = prelu_w[0];

    float h0 = a0 * inv + b1v.x;
    float h1 = a1 * inv + b1v.y;
    float h2 = a2 * inv + b1v.z;
    float h3 = a3 * inv + b1v.w;
    h0 = (h0 - mnv.x) * rsqrtf(vrv.x + BN_EPS_) * gmv.x + btv.x;
    h1 = (h1 - mnv.y) * rsqrtf(vrv.y + BN_EPS_) * gmv.y + btv.y;
    h2 = (h2 - mnv.z) * rsqrtf(vrv.z + BN_EPS_) * gmv.z + btv.z;
    h3 = (h3 - mnv.w) * rsqrtf(vrv.w + BN_EPS_) * gmv.w + btv.w;
    h0 = h0 >= 0.f ? h0 : pw * h0;
    h1 = h1 >= 0.f ? h1 : pw * h1;
    h2 = h2 >= 0.f ? h2 : pw * h2;
    h3 = h3 >= 0.f ? h3 : pw * h3;

    const float4 wgv = ((const float4*)Wg)[t];
    float part = h0 * wgv.x + h1 * wgv.y + h2 * wgv.z + h3 * wgv.w;
    #pragma unroll
    for (int o = 16; o; o >>= 1) part += __shfl_xor_sync(0xffffffffu, part, o);

    __shared__ float red[4];
    if ((t & 31) == 0) red[t >> 5] = part;
    __syncthreads();
    if (t == 0) {
        g_gout[node] = red[0] + red[1] + red[2] + red[3];
        g_dinv[node] = rsqrtf((float)cnt);
    }
}

// ---------------- GCNConv (OUT=1): warp per dst node ------------------------
__global__ void gcn_kernel(const float* __restrict__ bg, float* __restrict__ out) {
    int warp = (blockIdx.x * blockDim.x + threadIdx.x) >> 5;
    int lane = threadIdx.x & 31;
    if (warp >= N_NODES) return;
    int rs = g_offsets[warp], re = g_offsets[warp + 1];
    float di = g_dinv[warp];
    float s = (lane == 0) ? di * g_gout[warp] : 0.f;   // self loop
    for (int j = rs + lane; j < re; j += 32) {
        int src = g_csr_src[j];
        s += g_dinv[src] * g_gout[src];
    }
    #pragma unroll
    for (int o = 16; o; o >>= 1) s += __shfl_xor_sync(0xffffffffu, s, o);
    if (lane == 0) out[warp] = bg[0] + di * s;
}

// ---------------- launch ----------------------------------------------------
extern "C" void kernel_launch(void* const* d_in, const int* in_sizes, int n_in,
                              void* d_out, int out_size)
{
    const float* x    = (const float*)d_in[0];
    const int*   ei   = (const int*)  d_in[1];
    const float* Wl   = (const float*)d_in[2];
    const float* Wr   = (const float*)d_in[3];
    const float* att  = (const float*)d_in[4];
    const float* b1   = (const float*)d_in[5];
    const float* bn_g = (const float*)d_in[6];
    const float* bn_b = (const float*)d_in[7];
    const float* bn_m = (const float*)d_in[8];
    const float* bn_v = (const float*)d_in[9];
    const float* pw   = (const float*)d_in[10];
    const float* Wg   = (const float*)d_in[11];
    const float* bg   = (const float*)d_in[12];
    float* out = (float*)d_out;

    zero_counts_kernel<<<(N_NODES + 255) / 256, 256>>>();
    hist_kernel<<<(E_EDGES + 255) / 256, 256>>>(ei);
    scan_kernel<<<1, 1024>>>();
    scatter_kernel<<<(E_EDGES + 255) / 256, 256>>>(ei);

    dim3 gg((N_NODES + BM - 1) / BM, HC_ / BN, 2);
    gemm_xlxr<<<gg, 256>>>(x, Wl, Wr);

    agg_kernel<<<N_NODES, 128>>>(att, b1, bn_g, bn_b, bn_m, bn_v, pw, Wg);
    gcn_kernel<<<(N_NODES * 32 + 255) / 256, 256>>>(bg, out);
}

// round 3
// speedup vs baseline: 1.2916x; 1.2916x over previous
#include <cuda_runtime.h>
#include <cuda_fp16.h>
#include <cstdint>

#define N_NODES 25000
#define N_PAD   25088          // 196 * 128
#define E_EDGES 400000
#define F_IN_   133
#define HC_     512
#define KP      144            // padded K (multiple of 16)
#define TPAD    152            // SMEM row stride in halves (pad 8 -> conflict-free ldmatrix)
#define BN_EPS_ 1e-5f
#define NEG_SLOPE_ 0.2f
#define W_SCALE 64.0f
#define W_INV   0.015625f

// ---------------- device scratch (static) -----------------------------------
__device__ float  g_xl[(size_t)N_NODES * HC_];
__device__ float  g_xr[(size_t)N_NODES * HC_];
__device__ __half g_xh [(size_t)N_PAD * KP];
__device__ __half g_xlo[(size_t)N_PAD * KP];
__device__ __half g_wh [(size_t)1024 * KP];
__device__ __half g_wlo[(size_t)1024 * KP];
__device__ int   g_counts[N_NODES];
__device__ int   g_offsets[N_NODES + 1];
__device__ int   g_cursor[N_NODES];
__device__ int   g_csr_src[E_EDGES];
__device__ float g_gout[N_NODES];
__device__ float g_dinv[N_NODES];

// ---------------- helpers ---------------------------------------------------
__device__ __forceinline__ uint32_t smem_to_u32(const void* p) {
    uint32_t a;
    asm("{ .reg .u64 t; cvta.to.shared.u64 t, %1; cvt.u32.u64 %0, t; }"
        : "=r"(a) : "l"(p));
    return a;
}

#define LDM_X4(r, addr) \
    asm volatile("ldmatrix.sync.aligned.m8n8.x4.shared.b16 {%0,%1,%2,%3}, [%4];" \
        : "=r"((r)[0]), "=r"((r)[1]), "=r"((r)[2]), "=r"((r)[3]) : "r"(addr))

__device__ __forceinline__ void mma16816(float* d, const uint32_t* a,
                                         uint32_t b0, uint32_t b1) {
    asm volatile("mma.sync.aligned.m16n8k16.row.col.f32.f16.f16.f32 "
        "{%0,%1,%2,%3}, {%4,%5,%6,%7}, {%8,%9}, {%0,%1,%2,%3};"
        : "+f"(d[0]), "+f"(d[1]), "+f"(d[2]), "+f"(d[3])
        : "r"(a[0]), "r"(a[1]), "r"(a[2]), "r"(a[3]), "r"(b0), "r"(b1));
}

// ---------------- precision-split conversions -------------------------------
__global__ void conv_x_kernel(const float* __restrict__ x) {
    int i = blockIdx.x * blockDim.x + threadIdx.x;
    if (i >= N_PAD * KP) return;
    int r = i / KP, k = i - r * KP;
    float v = (r < N_NODES && k < F_IN_) ? x[(size_t)r * F_IN_ + k] : 0.f;
    __half h = __float2half_rn(v);
    g_xh[i]  = h;
    g_xlo[i] = __float2half_rn(v - __half2float(h));
}

__global__ void conv_w_kernel(const float* __restrict__ Wl,
                              const float* __restrict__ Wr) {
    int i = blockIdx.x * blockDim.x + threadIdx.x;
    if (i >= 1024 * KP) return;
    int n = i / KP, k = i - n * KP;
    float v = 0.f;
    if (k < F_IN_)
        v = W_SCALE * ((n < HC_) ? Wl[(size_t)k * HC_ + n]
                                 : Wr[(size_t)k * HC_ + (n - HC_)]);
    __half h = __float2half_rn(v);
    g_wh[i]  = h;
    g_wlo[i] = __float2half_rn(v - __half2float(h));
}

// ---------------- mma.sync GEMM ---------------------------------------------
// CTA: M=128 (blockIdx.x) x N=128 (blockIdx.y over [xl|xr] cols).
// K=144 entirely SMEM-resident. 8 warps, warptile 32x64.
#define TILE_H   (128 * TPAD)                 // halves per tile
#define SM_TOTAL (4 * TILE_H * 2)             // bytes (Ah, Al, Bh, Bl)

__global__ __launch_bounds__(256, 1) void gemm_mma_kernel() {
    extern __shared__ __half smem[];
    __half* Ah = smem;
    __half* Al = Ah + TILE_H;
    __half* Bh = Al + TILE_H;
    __half* Bl = Bh + TILE_H;

    const int tid = threadIdx.x;
    const size_t arow0 = (size_t)blockIdx.x * 128 * KP;
    const size_t brow0 = (size_t)blockIdx.y * 128 * KP;

    // load tiles: 2304 16B-chunks each (128 rows x 18 chunks of 8 halves)
    for (int idx = tid; idx < 2304; idx += 256) {
        int row = idx / 18;
        int j   = idx - row * 18;
        int so  = row * TPAD + j * 8;
        size_t go = (size_t)row * KP + j * 8;
        *(uint4*)(Ah + so) = *(const uint4*)(g_xh  + arow0 + go);
        *(uint4*)(Al + so) = *(const uint4*)(g_xlo + arow0 + go);
        *(uint4*)(Bh + so) = *(const uint4*)(g_wh  + brow0 + go);
        *(uint4*)(Bl + so) = *(const uint4*)(g_wlo + brow0 + go);
    }
    __syncthreads();

    const int wid = tid >> 5;
    const int lid = tid & 31;
    const int wm = (wid & 3) * 32;   // warp row offset in tile
    const int wn = (wid >> 2) * 64;  // warp col offset in tile

    float acc[2][8][4];
    #pragma unroll
    for (int mt = 0; mt < 2; mt++)
        #pragma unroll
        for (int nt = 0; nt < 8; nt++)
            #pragma unroll
            for (int j = 0; j < 4; j++) acc[mt][nt][j] = 0.f;

    // per-lane ldmatrix byte offsets (k0 added per step)
    const uint32_t a_base = smem_to_u32(Ah);
    const uint32_t al_base = smem_to_u32(Al);
    const uint32_t b_base = smem_to_u32(Bh);
    const uint32_t bl_base = smem_to_u32(Bl);

    // A: lanes 0-15 -> rows base+lane@k0, lanes 16-31 -> rows base+(lane-16)@k0+8
    const uint32_t a_off0 = ((uint32_t)(wm + (lid & 15)) * TPAD + (lid >> 4) * 8) * 2;
    // B: rows = n; lanes {0-7:n0-7@k0, 8-15:n0-7@k8, 16-23:n8-15@k0, 24-31:n8-15@k8}
    const uint32_t b_row = wn + (lid & 7) + ((lid >> 4) << 3);
    const uint32_t b_off0 = ((uint32_t)b_row * TPAD + ((lid >> 3) & 1) * 8) * 2;

    #pragma unroll
    for (int ks = 0; ks < 9; ks++) {
        const uint32_t kb = ks * 32;   // 16 halves = 32 bytes
        uint32_t a_hi[2][4], a_lo[2][4];
        #pragma unroll
        for (int mt = 0; mt < 2; mt++) {
            uint32_t ao = a_off0 + mt * (16 * TPAD * 2) + kb;
            LDM_X4(a_hi[mt], a_base + ao);
            LDM_X4(a_lo[mt], al_base + ao);
        }
        uint32_t b_hi[4][4], b_lo[4][4];
        #pragma unroll
        for (int np = 0; np < 4; np++) {
            uint32_t bo = b_off0 + np * (16 * TPAD * 2) + kb;
            LDM_X4(b_hi[np], b_base + bo);
            LDM_X4(b_lo[np], bl_base + bo);
        }
        #pragma unroll
        for (int mt = 0; mt < 2; mt++) {
            #pragma unroll
            for (int nt = 0; nt < 8; nt++) {
                const uint32_t* bh = &b_hi[nt >> 1][(nt & 1) * 2];
                const uint32_t* bl = &b_lo[nt >> 1][(nt & 1) * 2];
                mma16816(acc[mt][nt], a_hi[mt], bh[0], bh[1]);
                mma16816(acc[mt][nt], a_hi[mt], bl[0], bl[1]);
                mma16816(acc[mt][nt], a_lo[mt], bh[0], bh[1]);
            }
        }
    }

    // epilogue: scale by 1/64 and store to g_xl / g_xr
    const int gc0 = blockIdx.y * 128;
    float* obase = (gc0 < HC_) ? g_xl : g_xr;
    const int ocol0 = (gc0 < HC_) ? gc0 : gc0 - HC_;

    #pragma unroll
    for (int mt = 0; mt < 2; mt++) {
        int r0 = blockIdx.x * 128 + wm + mt * 16 + (lid >> 2);
        #pragma unroll
        for (int nt = 0; nt < 8; nt++) {
            int col = ocol0 + wn + nt * 8 + (lid & 3) * 2;
            if (r0 < N_NODES) {
                float2 v = make_float2(acc[mt][nt][0] * W_INV, acc[mt][nt][1] * W_INV);
                *(float2*)(obase + (size_t)r0 * HC_ + col) = v;
            }
            if (r0 + 8 < N_NODES) {
                float2 v = make_float2(acc[mt][nt][2] * W_INV, acc[mt][nt][3] * W_INV);
                *(float2*)(obase + (size_t)(r0 + 8) * HC_ + col) = v;
            }
        }
    }
}

// ---------------- CSR build -------------------------------------------------
__global__ void zero_counts_kernel() {
    int i = blockIdx.x * blockDim.x + threadIdx.x;
    if (i < N_NODES) g_counts[i] = 0;
}

__global__ void hist_kernel(const int* __restrict__ ei) {
    int e = blockIdx.x * blockDim.x + threadIdx.x;
    if (e < E_EDGES) atomicAdd(&g_counts[ei[E_EDGES + e]], 1);
}

__global__ __launch_bounds__(1024) void scan_kernel() {
    __shared__ int sh[1024];
    __shared__ int s_carry;
    const int t = threadIdx.x;
    if (t == 0) { s_carry = 0; g_offsets[0] = 0; }
    __syncthreads();
    for (int base = 0; base < N_NODES; base += 1024) {
        int i = base + t;
        int v = (i < N_NODES) ? g_counts[i] : 0;
        sh[t] = v;
        __syncthreads();
        #pragma unroll
        for (int d = 1; d < 1024; d <<= 1) {
            int val = sh[t];
            int add = (t >= d) ? sh[t - d] : 0;
            __syncthreads();
            sh[t] = val + add;
            __syncthreads();
        }
        int incl = sh[t];
        int carry = s_carry;
        if (i < N_NODES) {
            g_offsets[i + 1] = carry + incl;
            g_cursor[i] = carry + incl - v;
        }
        __syncthreads();
        if (t == 1023) s_carry = carry + incl;
        __syncthreads();
    }
}

__global__ void scatter_kernel(const int* __restrict__ ei) {
    int e = blockIdx.x * blockDim.x + threadIdx.x;
    if (e < E_EDGES) {
        int d = ei[E_EDGES + e];
        int p = atomicAdd(&g_cursor[d], 1);
        g_csr_src[p] = ei[e];
    }
}

// ---------------- GATv2 aggregation + b1 + BN + PReLU + (.@Wg) --------------
__global__ __launch_bounds__(128) void agg_kernel(
    const float* __restrict__ att,  const float* __restrict__ b1,
    const float* __restrict__ bn_g, const float* __restrict__ bn_b,
    const float* __restrict__ bn_m, const float* __restrict__ bn_v,
    const float* __restrict__ prelu_w, const float* __restrict__ Wg)
{
    const int node = blockIdx.x;
    const int t = threadIdx.x;
    const float4* __restrict__ xl4 = (const float4*)g_xl;

    const float4 xr_v  = ((const float4*)(g_xr + (size_t)node * HC_))[t];
    const float4 att_v = ((const float4*)att)[t];

    const int rs = g_offsets[node];
    const int re = g_offsets[node + 1];
    const int cnt = re - rs + 1;

    float a0 = 0.f, a1 = 0.f, a2 = 0.f, a3 = 0.f;
    float m = __int_as_float(0xff800000);
    float den = 0.f;

    float4 v = __ldg(&xl4[(size_t)node * (HC_ / 4) + t]);
    for (int k = 0; k < cnt; k++) {
        float4 nv = v;
        if (k + 1 < cnt) {
            int ns = g_csr_src[rs + k];
            nv = __ldg(&xl4[(size_t)ns * (HC_ / 4) + t]);
        }
        float s0 = v.x + xr_v.x; s0 = s0 > 0.f ? s0 : NEG_SLOPE_ * s0;
        float s1 = v.y + xr_v.y; s1 = s1 > 0.f ? s1 : NEG_SLOPE_ * s1;
        float s2 = v.z + xr_v.z; s2 = s2 > 0.f ? s2 : NEG_SLOPE_ * s2;
        float s3 = v.w + xr_v.w; s3 = s3 > 0.f ? s3 : NEG_SLOPE_ * s3;
        float p = att_v.x * s0 + att_v.y * s1 + att_v.z * s2 + att_v.w * s3;
        p += __shfl_xor_sync(0xffffffffu, p, 1);
        p += __shfl_xor_sync(0xffffffffu, p, 2);
        p += __shfl_xor_sync(0xffffffffu, p, 4);
        p += __shfl_xor_sync(0xffffffffu, p, 8);
        float e  = p;
        float mn = fmaxf(m, e);
        float sc = __expf(m - mn);
        float w  = __expf(e - mn);
        den = den * sc + w;
        a0 = a0 * sc + w * v.x;
        a1 = a1 * sc + w * v.y;
        a2 = a2 * sc + w * v.z;
        a3 = a3 * sc + w * v.w;
        m = mn;
        v = nv;
    }

    const float inv = 1.f / den;
    const float4 b1v = ((const float4*)b1)[t];
    const float4 gmv = ((const float4*)bn_g)[t];
    const float4 btv = ((const float4*)bn_b)[t];
    const float4 mnv = ((const float4*)bn_m)[t];
    const float4 vrv = ((const float4*)bn_v)[t];
    const float pw = prelu_w[0];

    float h0 = a0 * inv + b1v.x;
    float h1 = a1 * inv + b1v.y;
    float h2 = a2 * inv + b1v.z;
    float h3 = a3 * inv + b1v.w;
    h0 = (h0 - mnv.x) * rsqrtf(vrv.x + BN_EPS_) * gmv.x + btv.x;
    h1 = (h1 - mnv.y) * rsqrtf(vrv.y + BN_EPS_) * gmv.y + btv.y;
    h2 = (h2 - mnv.z) * rsqrtf(vrv.z + BN_EPS_) * gmv.z + btv.z;
    h3 = (h3 - mnv.w) * rsqrtf(vrv.w + BN_EPS_) * gmv.w + btv.w;
    h0 = h0 >= 0.f ? h0 : pw * h0;
    h1 = h1 >= 0.f ? h1 : pw * h1;
    h2 = h2 >= 0.f ? h2 : pw * h2;
    h3 = h3 >= 0.f ? h3 : pw * h3;

    const float4 wgv = ((const float4*)Wg)[t];
    float part = h0 * wgv.x + h1 * wgv.y + h2 * wgv.z + h3 * wgv.w;
    #pragma unroll
    for (int o = 16; o; o >>= 1) part += __shfl_xor_sync(0xffffffffu, part, o);

    __shared__ float red[4];
    if ((t & 31) == 0) red[t >> 5] = part;
    __syncthreads();
    if (t == 0) {
        g_gout[node] = red[0] + red[1] + red[2] + red[3];
        g_dinv[node] = rsqrtf((float)cnt);
    }
}

// ---------------- GCNConv (OUT=1) -------------------------------------------
__global__ void gcn_kernel(const float* __restrict__ bg, float* __restrict__ out) {
    int warp = (blockIdx.x * blockDim.x + threadIdx.x) >> 5;
    int lane = threadIdx.x & 31;
    if (warp >= N_NODES) return;
    int rs = g_offsets[warp], re = g_offsets[warp + 1];
    float di = g_dinv[warp];
    float s = (lane == 0) ? di * g_gout[warp] : 0.f;
    for (int j = rs + lane; j < re; j += 32) {
        int src = g_csr_src[j];
        s += g_dinv[src] * g_gout[src];
    }
    #pragma unroll
    for (int o = 16; o; o >>= 1) s += __shfl_xor_sync(0xffffffffu, s, o);
    if (lane == 0) out[warp] = bg[0] + di * s;
}

// ---------------- launch ----------------------------------------------------
extern "C" void kernel_launch(void* const* d_in, const int* in_sizes, int n_in,
                              void* d_out, int out_size)
{
    const float* x    = (const float*)d_in[0];
    const int*   ei   = (const int*)  d_in[1];
    const float* Wl   = (const float*)d_in[2];
    const float* Wr   = (const float*)d_in[3];
    const float* att  = (const float*)d_in[4];
    const float* b1   = (const float*)d_in[5];
    const float* bn_g = (const float*)d_in[6];
    const float* bn_b = (const float*)d_in[7];
    const float* bn_m = (const float*)d_in[8];
    const float* bn_v = (const float*)d_in[9];
    const float* pw   = (const float*)d_in[10];
    const float* Wg   = (const float*)d_in[11];
    const float* bg   = (const float*)d_in[12];
    float* out = (float*)d_out;

    cudaFuncSetAttribute(gemm_mma_kernel,
                         cudaFuncAttributeMaxDynamicSharedMemorySize, SM_TOTAL);

    zero_counts_kernel<<<(N_NODES + 255) / 256, 256>>>();
    hist_kernel<<<(E_EDGES + 255) / 256, 256>>>(ei);
    scan_kernel<<<1, 1024>>>();
    scatter_kernel<<<(E_EDGES + 255) / 256, 256>>>(ei);

    conv_x_kernel<<<(N_PAD * KP + 255) / 256, 256>>>(x);
    conv_w_kernel<<<(1024 * KP + 255) / 256, 256>>>(Wl, Wr);

    dim3 gg(N_PAD / 128, 1024 / 128);
    gemm_mma_kernel<<<gg, 256, SM_TOTAL>>>();

    agg_kernel<<<N_NODES, 128>>>(att, b1, bn_g, bn_b, bn_m, bn_v, pw, Wg);
    gcn_kernel<<<(N_NODES * 32 + 255) / 256, 256>>>(bg, out);
}